// round 16
// baseline (speedup 1.0000x reference)
#include <cuda_runtime.h>
#include <cstdint>

// ---- int32/int64 robustness: harness may deliver int64 refs as int32.
__device__ __forceinline__ bool buf_is_i64(const void* p) {
    const int* q = (const int*)p;
    return (q[1] == 0) && (q[3] == 0) && (q[5] == 0);
}
__device__ __forceinline__ long long load_i(const void* p, int i, bool is64) {
    return is64 ? ((const long long*)p)[i] : (long long)((const int*)p)[i];
}

#define TPB   256
#define NWARP (TPB / 32)
#define MAXG  64

// Per-launch schedule (rewritten deterministically every launch by setup_kernel,
// so it is CUDA-graph-replay safe).
__device__ int g_order[MAXG];   // group ids sorted by descending size
__device__ int g_start[MAXG];   // channel start of each group id
__device__ int g_len[MAXG];     // size of each group id

// ---------------- Setup: sort groups by size (LPT schedule) ----------------
__global__ void setup_kernel(const void* __restrict__ group_sizes, int G)
{
    if (threadIdx.x != 0) return;
    const bool gs64 = buf_is_i64(group_sizes);
    int acc = 0;
    for (int k = 0; k < G; ++k) {
        const int len = (int)load_i(group_sizes, k, gs64);
        g_start[k] = acc;
        g_len[k]   = len;
        acc += len;
    }
    // insertion sort of ids by descending length (G <= 64, trivial)
    int ord[MAXG];
    for (int k = 0; k < G; ++k) ord[k] = k;
    for (int i = 1; i < G; ++i) {
        const int id = ord[i];
        const int keylen = g_len[id];
        int j = i - 1;
        while (j >= 0 && g_len[ord[j]] < keylen) { ord[j + 1] = ord[j]; --j; }
        ord[j + 1] = id;
    }
    for (int k = 0; k < G; ++k) g_order[k] = ord[k];
}

// ---------------- Fused group-norm: one block per (rank, sample) -----------
// Phase A: MLP-8 row streaming for sum/sumsq. Phase B: immediate re-read of
// the same rows (hot in L2) + fma + streaming store. Row-units: glen is a
// multiple of NWARP=8 for all sizes {8,16,24,32} -> no idle warps.
__global__ void __launch_bounds__(TPB, 6) vgn_fused_kernel(
    const float* __restrict__ x,
    float* __restrict__ out,
    const void* __restrict__ indexes,
    const float* __restrict__ weight,
    const float* __restrict__ bias,
    int C, int G, int HW4, int N)
{
    __shared__ int   s_idx[MAXG];
    __shared__ float s_w1[NWARP], s_w2[NWARP];
    __shared__ float s_mu, s_ivar;

    const int tid  = threadIdx.x;
    const int wid  = tid >> 5;
    const int lane = tid & 31;

    const int k = blockIdx.x / N;        // size rank (0 = largest)
    const int n = blockIdx.x - k * N;    // sample
    const int g      = g_order[k];
    const int cstart = g_start[g];
    const int glen   = g_len[g];
    const int nfull  = HW4 & ~255;

    if (tid < glen) {
        const bool ix64 = buf_is_i64(indexes);
        s_idx[tid] = (int)load_i(indexes, n * C + cstart + tid, ix64);
    }
    __syncthreads();

    // ---------------- Phase A: stats, MLP-8 --------------------------------
    float s1a = 0.f, s2a = 0.f, s1b = 0.f, s2b = 0.f;
    for (int j = wid; j < glen; j += NWARP) {
        const float4* __restrict__ p =
            (const float4*)(x + (size_t)s_idx[j] * (size_t)(HW4 * 4));
        for (int j0 = 0; j0 < nfull; j0 += 256) {
            float4 v[8];
            #pragma unroll
            for (int kk = 0; kk < 8; ++kk) v[kk] = p[j0 + (kk << 5) + lane];
            #pragma unroll
            for (int kk = 0; kk < 8; kk += 2) {
                s1a += (v[kk].x + v[kk].y) + (v[kk].z + v[kk].w);
                s2a += v[kk].x*v[kk].x + v[kk].y*v[kk].y
                     + v[kk].z*v[kk].z + v[kk].w*v[kk].w;
                s1b += (v[kk+1].x + v[kk+1].y) + (v[kk+1].z + v[kk+1].w);
                s2b += v[kk+1].x*v[kk+1].x + v[kk+1].y*v[kk+1].y
                     + v[kk+1].z*v[kk+1].z + v[kk+1].w*v[kk+1].w;
            }
        }
        for (int jj = nfull + lane; jj < HW4; jj += 32) {
            float4 v = p[jj];
            s1a += (v.x + v.y) + (v.z + v.w);
            s2a += v.x*v.x + v.y*v.y + v.z*v.z + v.w*v.w;
        }
    }
    float s1 = s1a + s1b, s2 = s2a + s2b;
    #pragma unroll
    for (int o = 16; o; o >>= 1) {
        s1 += __shfl_down_sync(0xffffffffu, s1, o);
        s2 += __shfl_down_sync(0xffffffffu, s2, o);
    }
    if (lane == 0) { s_w1[wid] = s1; s_w2[wid] = s2; }
    __syncthreads();
    if (tid == 0) {
        float t1 = 0.f, t2 = 0.f;
        #pragma unroll
        for (int kk = 0; kk < NWARP; ++kk) { t1 += s_w1[kk]; t2 += s_w2[kk]; }
        const float cnt  = (float)glen * (float)(HW4 * 4);
        const float mu   = t1 / cnt;
        const float var  = (t2 - cnt * mu * mu) / (cnt - 1.0f);
        s_mu = mu;
        s_ivar = rsqrtf(var + 1e-12f);
    }
    __syncthreads();
    const float mu = s_mu, ivar = s_ivar;

    // ---------------- Phase B: normalize, MLP-4 (L2-hit reads) -------------
    const int nfull4 = HW4 & ~127;
    for (int j = wid; j < glen; j += NWARP) {
        const int c = cstart + j;
        const float a   = ivar * weight[c];
        const float bsh = bias[c] - mu * a;
        const size_t off = (size_t)s_idx[j] * (size_t)(HW4 * 4);
        const float4* __restrict__ px = (const float4*)(x + off);
        float4*       __restrict__ po = (float4*)(out + off);
        for (int j0 = 0; j0 < nfull4; j0 += 128) {
            float4 v[4];
            #pragma unroll
            for (int kk = 0; kk < 4; ++kk) v[kk] = __ldcs(&px[j0 + (kk << 5) + lane]);
            #pragma unroll
            for (int kk = 0; kk < 4; ++kk) {
                v[kk].x = fmaf(v[kk].x, a, bsh);
                v[kk].y = fmaf(v[kk].y, a, bsh);
                v[kk].z = fmaf(v[kk].z, a, bsh);
                v[kk].w = fmaf(v[kk].w, a, bsh);
            }
            #pragma unroll
            for (int kk = 0; kk < 4; ++kk) __stcs(&po[j0 + (kk << 5) + lane], v[kk]);
        }
        for (int jj = nfull4 + lane; jj < HW4; jj += 32) {
            float4 v = __ldcs(&px[jj]);
            v.x = fmaf(v.x, a, bsh); v.y = fmaf(v.y, a, bsh);
            v.z = fmaf(v.z, a, bsh); v.w = fmaf(v.w, a, bsh);
            __stcs(&po[jj], v);
        }
    }
}

extern "C" void kernel_launch(void* const* d_in, const int* in_sizes, int n_in,
                              void* d_out, int out_size)
{
    const float* x       = (const float*)d_in[0];
    const float* weight  = (const float*)d_in[1];
    const float* bias    = (const float*)d_in[2];
    const void*  gsizes  = d_in[3];
    const void*  indexes = d_in[4];
    float* out = (float*)d_out;

    const int C   = in_sizes[1];
    const int G   = in_sizes[3];
    const int NC  = in_sizes[4];
    const int HW  = in_sizes[0] / NC;
    const int HW4 = HW / 4;
    const int N   = NC / C;
    const int NG  = N * G;

    setup_kernel<<<1, 32>>>(gsizes, G);
    vgn_fused_kernel<<<NG, TPB>>>(x, out, indexes, weight, bias, C, G, HW4, N);
}